// round 1
// baseline (speedup 1.0000x reference)
#include <cuda_runtime.h>
#include <cuda_bf16.h>

#define N_NODES 50000
#define IN_FEAT 512
#define OUT_FEAT 128
#define N_EDGES 800000

// Scratch for the GEMM result x = feat @ W  (25.6 MB). Device global since
// allocations are forbidden.
__device__ float g_x[(size_t)N_NODES * OUT_FEAT];

// ---------------------------------------------------------------------------
// Kernel 1: fp32 SGEMM  C[M,128] = A[M,512] * B[512,128]
// Tiling: BM=128, BN=128, BK=8; 256 threads; 8x8 micro-tile per thread.
// ---------------------------------------------------------------------------
#define BM 128
#define BN 128
#define BK 8
#define TM 8
#define TN 8

__global__ void __launch_bounds__(256) gemm_kernel(const float* __restrict__ A,
                                                   const float* __restrict__ B) {
    __shared__ float As[BK][BM];   // A tile stored transposed for conflict-free reads
    __shared__ float Bs[BK][BN];

    const int tid = threadIdx.x;
    const int tx  = tid & 15;      // 16 thread-cols * TN(8)  = 128
    const int ty  = tid >> 4;      // 16 thread-rows * TM(8)  = 128
    const int row0 = blockIdx.x * BM;

    // Global-load index mapping (one float4 per thread per tile)
    const int ar = tid >> 1;          // 0..127   A tile row
    const int ac = (tid & 1) * 4;     // 0 or 4   A tile col
    const int br = tid >> 5;          // 0..7     B tile row
    const int bc = (tid & 31) * 4;    // 0..124   B tile col

    float acc[TM][TN];
    #pragma unroll
    for (int m = 0; m < TM; m++)
        #pragma unroll
        for (int n = 0; n < TN; n++) acc[m][n] = 0.0f;

    for (int k0 = 0; k0 < IN_FEAT; k0 += BK) {
        // Load A tile (guarded on M edge), store transposed
        float4 av = make_float4(0.f, 0.f, 0.f, 0.f);
        const int arow = row0 + ar;
        if (arow < N_NODES)
            av = *reinterpret_cast<const float4*>(A + (size_t)arow * IN_FEAT + k0 + ac);
        As[ac + 0][ar] = av.x;
        As[ac + 1][ar] = av.y;
        As[ac + 2][ar] = av.z;
        As[ac + 3][ar] = av.w;

        // Load B tile (N=128 exact, K=512 exact: no guard needed)
        float4 bv = *reinterpret_cast<const float4*>(B + (size_t)(k0 + br) * OUT_FEAT + bc);
        *reinterpret_cast<float4*>(&Bs[br][bc]) = bv;

        __syncthreads();

        #pragma unroll
        for (int k = 0; k < BK; k++) {
            float ra[TM], rb[TN];
            #pragma unroll
            for (int m = 0; m < TM; m++) ra[m] = As[k][ty * TM + m];
            #pragma unroll
            for (int n = 0; n < TN; n++) rb[n] = Bs[k][tx * TN + n];
            #pragma unroll
            for (int m = 0; m < TM; m++)
                #pragma unroll
                for (int n = 0; n < TN; n++)
                    acc[m][n] = fmaf(ra[m], rb[n], acc[m][n]);
        }
        __syncthreads();
    }

    // Store C tile
    #pragma unroll
    for (int m = 0; m < TM; m++) {
        const int r = row0 + ty * TM + m;
        if (r < N_NODES) {
            #pragma unroll
            for (int n = 0; n < TN; n += 4) {
                float4 v = make_float4(acc[m][n], acc[m][n + 1],
                                       acc[m][n + 2], acc[m][n + 3]);
                *reinterpret_cast<float4*>(g_x + (size_t)r * OUT_FEAT + tx * TN + n) = v;
            }
        }
    }
}

// ---------------------------------------------------------------------------
// Kernel 2: SpMM (rows sorted -> per-node segment via binary search) + multispike
// One block of 128 threads per node; thread t owns output column t.
// ---------------------------------------------------------------------------
__global__ void __launch_bounds__(128) spmm_kernel(const int*   __restrict__ rows,
                                                   const int*   __restrict__ cols,
                                                   const float* __restrict__ ew,
                                                   float*       __restrict__ out) {
    const int node = blockIdx.x;
    const int tid  = threadIdx.x;

    // lower_bound(rows, node)
    int lo = 0, hi = N_EDGES;
    while (lo < hi) {
        int mid = (lo + hi) >> 1;
        if (rows[mid] < node) lo = mid + 1; else hi = mid;
    }
    const int start = lo;
    // upper_bound(rows, node)
    hi = N_EDGES;
    while (lo < hi) {
        int mid = (lo + hi) >> 1;
        if (rows[mid] <= node) lo = mid + 1; else hi = mid;
    }
    const int end = lo;

    float acc = 0.0f;
    for (int e = start; e < end; e++) {
        const float w = ew[e];
        const int   c = cols[e];
        acc = fmaf(w, g_x[(size_t)c * OUT_FEAT + tid], acc);
    }

    // multispike: floor(clamp(4x, 0, 4) + 0.5) / 4
    float v = fminf(fmaxf(4.0f * acc, 0.0f), 4.0f);
    v = floorf(v + 0.5f) * 0.25f;
    out[(size_t)node * OUT_FEAT + tid] = v;
}

// ---------------------------------------------------------------------------
extern "C" void kernel_launch(void* const* d_in, const int* in_sizes, int n_in,
                              void* d_out, int out_size) {
    const float* feat   = (const float*)d_in[0];
    const float* weight = (const float*)d_in[1];
    const int*   rows   = (const int*)  d_in[2];
    const int*   cols   = (const int*)  d_in[3];
    const float* ew     = (const float*)d_in[4];
    float*       out    = (float*)d_out;

    gemm_kernel<<<(N_NODES + BM - 1) / BM, 256>>>(feat, weight);
    spmm_kernel<<<N_NODES, 128>>>(rows, cols, ew, out);
}

// round 3
// speedup vs baseline: 1.7455x; 1.7455x over previous
#include <cuda_runtime.h>
#include <cuda_bf16.h>

#define N_NODES 50000
#define IN_FEAT 512
#define OUT_FEAT 128
#define N_EDGES 800000

// Scratch (allocations forbidden -> device globals)
__device__ float g_x[(size_t)N_NODES * OUT_FEAT];      // GEMM result, 25.6 MB
__device__ int   g_row_ptr[N_NODES + 1];               // CSR row pointers

// ---------------------------------------------------------------------------
// packed fp32x2 helpers (sm_103a FFMA2 — bitwise == two fmaf)
// ---------------------------------------------------------------------------
typedef unsigned long long ull;

__device__ __forceinline__ ull pack2_same(float x) {
    ull r;
    asm("mov.b64 %0, {%1, %1};" : "=l"(r) : "f"(x));
    return r;
}
__device__ __forceinline__ void fma2(ull& d, ull a, ull b) {
    asm("fma.rn.f32x2 %0, %1, %2, %3;" : "=l"(d) : "l"(a), "l"(b), "l"(d));
}
__device__ __forceinline__ float2 unpack2(ull v) {
    float2 f;
    asm("mov.b64 {%0, %1}, %2;" : "=f"(f.x), "=f"(f.y) : "l"(v));
    return f;
}

// ---------------------------------------------------------------------------
// Kernel 1: fp32x2 SGEMM  g_x[M,128] = A[M,512] * B[512,128]
// BM=128, BN=128, BK=8, 256 threads, 8x8 micro-tile (FMA2 packs the N dim).
// Thread (tx 0..15, ty 0..15) owns rows {4ty..4ty+3, 64+4ty..} and
// cols {4tx..4tx+3, 64+4tx..} -> lanes 0..15 read contiguous 16B from smem
// (conflict-free LDS.128). Double-buffered smem tiles.
// ---------------------------------------------------------------------------
#define BM 128
#define BK 8

__global__ void __launch_bounds__(256) gemm_kernel(const float* __restrict__ A,
                                                   const float* __restrict__ B) {
    __shared__ float As[2][BK][BM];   // A tile transposed
    __shared__ float Bs[2][BK][128];

    const int tid = threadIdx.x;
    const int tx  = tid & 15;
    const int ty  = tid >> 4;
    const int row0 = blockIdx.x * BM;

    // global-load mapping (one float4 per thread per tile)
    const int ar = tid >> 1;          // 0..127
    const int ac = (tid & 1) * 4;     // 0 or 4
    const int br = tid >> 5;          // 0..7
    const int bc = (tid & 31) * 4;    // 0..124

    ull acc[8][4];                    // 8 rows x 8 cols (4 packed pairs)
    #pragma unroll
    for (int m = 0; m < 8; m++)
        #pragma unroll
        for (int j = 0; j < 4; j++) acc[m][j] = 0ull;

    // ---- load tile 0 ----
    {
        float4 av = make_float4(0.f, 0.f, 0.f, 0.f);
        const int arow = row0 + ar;
        if (arow < N_NODES)
            av = *reinterpret_cast<const float4*>(A + (size_t)arow * IN_FEAT + ac);
        As[0][ac + 0][ar] = av.x;
        As[0][ac + 1][ar] = av.y;
        As[0][ac + 2][ar] = av.z;
        As[0][ac + 3][ar] = av.w;
        float4 bv = *reinterpret_cast<const float4*>(B + (size_t)br * OUT_FEAT + bc);
        *reinterpret_cast<float4*>(&Bs[0][br][bc]) = bv;
    }
    __syncthreads();

    const int NT = IN_FEAT / BK;      // 64 tiles
    int buf = 0;
    for (int t = 0; t < NT; t++) {
        // prefetch next tile into registers
        float4 av = make_float4(0.f, 0.f, 0.f, 0.f);
        float4 bv = make_float4(0.f, 0.f, 0.f, 0.f);
        if (t + 1 < NT) {
            const int k0 = (t + 1) * BK;
            const int arow = row0 + ar;
            if (arow < N_NODES)
                av = *reinterpret_cast<const float4*>(A + (size_t)arow * IN_FEAT + k0 + ac);
            bv = *reinterpret_cast<const float4*>(B + (size_t)(k0 + br) * OUT_FEAT + bc);
        }

        // compute on current buffer
        #pragma unroll
        for (int k = 0; k < BK; k++) {
            const float4 a0 = *reinterpret_cast<const float4*>(&As[buf][k][ty * 4]);
            const float4 a1 = *reinterpret_cast<const float4*>(&As[buf][k][64 + ty * 4]);
            const ulonglong2 b0 = *reinterpret_cast<const ulonglong2*>(&Bs[buf][k][tx * 4]);
            const ulonglong2 b1 = *reinterpret_cast<const ulonglong2*>(&Bs[buf][k][64 + tx * 4]);
            ull rb[4] = {b0.x, b0.y, b1.x, b1.y};
            float ra[8] = {a0.x, a0.y, a0.z, a0.w, a1.x, a1.y, a1.z, a1.w};
            #pragma unroll
            for (int m = 0; m < 8; m++) {
                ull ra2 = pack2_same(ra[m]);
                #pragma unroll
                for (int j = 0; j < 4; j++) fma2(acc[m][j], ra2, rb[j]);
            }
        }

        // store prefetched tile into the other buffer
        if (t + 1 < NT) {
            const int nb = buf ^ 1;
            As[nb][ac + 0][ar] = av.x;
            As[nb][ac + 1][ar] = av.y;
            As[nb][ac + 2][ar] = av.z;
            As[nb][ac + 3][ar] = av.w;
            *reinterpret_cast<float4*>(&Bs[nb][br][bc]) = bv;
            __syncthreads();
            buf = nb;
        }
    }

    // ---- store C ----
    #pragma unroll
    for (int mc = 0; mc < 2; mc++) {
        #pragma unroll
        for (int mr = 0; mr < 4; mr++) {
            const int m = mc * 4 + mr;
            const int r = row0 + mc * 64 + ty * 4 + mr;
            if (r < N_NODES) {
                float2 p0 = unpack2(acc[m][0]);
                float2 p1 = unpack2(acc[m][1]);
                float2 p2 = unpack2(acc[m][2]);
                float2 p3 = unpack2(acc[m][3]);
                float4 v0 = make_float4(p0.x, p0.y, p1.x, p1.y);
                float4 v1 = make_float4(p2.x, p2.y, p3.x, p3.y);
                *reinterpret_cast<float4*>(g_x + (size_t)r * OUT_FEAT + tx * 4)      = v0;
                *reinterpret_cast<float4*>(g_x + (size_t)r * OUT_FEAT + 64 + tx * 4) = v1;
            }
        }
    }
}

// ---------------------------------------------------------------------------
// Kernel 2: build row_ptr from sorted rows (O(E), replaces binary search)
// ---------------------------------------------------------------------------
__global__ void __launch_bounds__(256) build_rowptr_kernel(const int* __restrict__ rows) {
    const int e = blockIdx.x * 256 + threadIdx.x;
    if (e >= N_EDGES) return;
    const int r    = rows[e];
    const int prev = (e == 0) ? -1 : rows[e - 1];
    for (int i = prev + 1; i <= r; i++) g_row_ptr[i] = e;
    if (e == N_EDGES - 1)
        for (int i = r + 1; i <= N_NODES; i++) g_row_ptr[i] = N_EDGES;
}

// ---------------------------------------------------------------------------
// Kernel 3: SpMM + multispike. One warp per node; lane owns 4 columns (float4).
// ---------------------------------------------------------------------------
__global__ void __launch_bounds__(256) spmm_kernel(const int*   __restrict__ cols,
                                                   const float* __restrict__ ew,
                                                   float*       __restrict__ out) {
    const int node = blockIdx.x * 8 + (threadIdx.x >> 5);
    if (node >= N_NODES) return;
    const int lane = threadIdx.x & 31;

    const int start = g_row_ptr[node];
    const int end   = g_row_ptr[node + 1];

    float4 acc = make_float4(0.f, 0.f, 0.f, 0.f);
    int e = start;
    for (; e + 1 < end; e += 2) {
        const int   c0 = cols[e],     c1 = cols[e + 1];
        const float w0 = ew[e],       w1 = ew[e + 1];
        const float4 v0 = *reinterpret_cast<const float4*>(g_x + (size_t)c0 * OUT_FEAT + lane * 4);
        const float4 v1 = *reinterpret_cast<const float4*>(g_x + (size_t)c1 * OUT_FEAT + lane * 4);
        acc.x = fmaf(w0, v0.x, acc.x);
        acc.y = fmaf(w0, v0.y, acc.y);
        acc.z = fmaf(w0, v0.z, acc.z);
        acc.w = fmaf(w0, v0.w, acc.w);
        acc.x = fmaf(w1, v1.x, acc.x);
        acc.y = fmaf(w1, v1.y, acc.y);
        acc.z = fmaf(w1, v1.z, acc.z);
        acc.w = fmaf(w1, v1.w, acc.w);
    }
    if (e < end) {
        const int   c0 = cols[e];
        const float w0 = ew[e];
        const float4 v0 = *reinterpret_cast<const float4*>(g_x + (size_t)c0 * OUT_FEAT + lane * 4);
        acc.x = fmaf(w0, v0.x, acc.x);
        acc.y = fmaf(w0, v0.y, acc.y);
        acc.z = fmaf(w0, v0.z, acc.z);
        acc.w = fmaf(w0, v0.w, acc.w);
    }

    // multispike: floor(clamp(4x,0,4)+0.5)/4
    float4 o;
    o.x = floorf(fminf(fmaxf(4.f * acc.x, 0.f), 4.f) + 0.5f) * 0.25f;
    o.y = floorf(fminf(fmaxf(4.f * acc.y, 0.f), 4.f) + 0.5f) * 0.25f;
    o.z = floorf(fminf(fmaxf(4.f * acc.z, 0.f), 4.f) + 0.5f) * 0.25f;
    o.w = floorf(fminf(fmaxf(4.f * acc.w, 0.f), 4.f) + 0.5f) * 0.25f;
    *reinterpret_cast<float4*>(out + (size_t)node * OUT_FEAT + lane * 4) = o;
}

// ---------------------------------------------------------------------------
extern "C" void kernel_launch(void* const* d_in, const int* in_sizes, int n_in,
                              void* d_out, int out_size) {
    const float* feat   = (const float*)d_in[0];
    const float* weight = (const float*)d_in[1];
    const int*   rows   = (const int*)  d_in[2];
    const int*   cols   = (const int*)  d_in[3];
    const float* ew     = (const float*)d_in[4];
    float*       out    = (float*)d_out;

    build_rowptr_kernel<<<(N_EDGES + 255) / 256, 256>>>(rows);
    gemm_kernel<<<(N_NODES + BM - 1) / BM, 256>>>(feat, weight);
    spmm_kernel<<<(N_NODES + 7) / 8, 256>>>(cols, ew, out);
}

// round 14
// speedup vs baseline: 2.5849x; 1.4809x over previous
#include <cuda_runtime.h>
#include <cuda_fp16.h>
#include <cstdint>

#define N_NODES 50000
#define IN_FEAT 512
#define OUT_FEAT 128
#define N_EDGES 800000

// ---------------------------------------------------------------------------
// Scratch (allocations forbidden -> device globals)
// ---------------------------------------------------------------------------
__device__ float  g_x[(size_t)N_NODES * OUT_FEAT];     // GEMM result (25.6 MB)
__device__ int    g_row_ptr[N_NODES + 1];
__device__ __half g_Bh[OUT_FEAT * IN_FEAT];            // W^T hi  [128 n][512 k]
__device__ __half g_Bl[OUT_FEAT * IN_FEAT];            // W^T lo  (unscaled residual)

// ---------------------------------------------------------------------------
// fp16 2-way split: a = h + l + r,  |r| <~ 2^-22 |a|
// l stored UNscaled -> all 4 partial products share one accumulator.
// ---------------------------------------------------------------------------
__device__ __forceinline__ void split2(float a, __half& h, __half& l) {
    h = __float2half_rn(a);
    l = __float2half_rn(a - __half2float(h));
}

// mma.sync m16n8k16 f16 -> f32 (plain sm_80+ ISA; assembles at sm_103)
#define MMA16816(c, a, b)                                                     \
    asm volatile(                                                             \
        "mma.sync.aligned.m16n8k16.row.col.f32.f16.f16.f32 "                  \
        "{%0,%1,%2,%3}, {%4,%5,%6,%7}, {%8,%9}, {%0,%1,%2,%3};"               \
        : "+f"((c)[0]), "+f"((c)[1]), "+f"((c)[2]), "+f"((c)[3])              \
        : "r"((a)[0]), "r"((a)[1]), "r"((a)[2]), "r"((a)[3]),                 \
          "r"((b)[0]), "r"((b)[1]))

// ---------------------------------------------------------------------------
// Kernel A: split W (fp32 [512,128]) into transposed fp16 hi/lo [128][512]
// ---------------------------------------------------------------------------
__global__ void __launch_bounds__(256) bsplit_kernel(const float* __restrict__ W) {
    const int idx = blockIdx.x * 256 + threadIdx.x;
    if (idx >= IN_FEAT * OUT_FEAT) return;
    const int k = idx >> 7;
    const int n = idx & 127;
    __half h, l;
    split2(W[idx], h, l);
    const int o = n * IN_FEAT + k;
    g_Bh[o] = h;
    g_Bl[o] = l;
}

// ---------------------------------------------------------------------------
// Kernel B: row_ptr from sorted rows
// ---------------------------------------------------------------------------
__global__ void __launch_bounds__(256) build_rowptr_kernel(const int* __restrict__ rows) {
    const int e = blockIdx.x * 256 + threadIdx.x;
    if (e >= N_EDGES) return;
    const int r    = rows[e];
    const int prev = (e == 0) ? -1 : rows[e - 1];
    for (int i = prev + 1; i <= r; i++) g_row_ptr[i] = e;
    if (e == N_EDGES - 1)
        for (int i = r + 1; i <= N_NODES; i++) g_row_ptr[i] = N_EDGES;
}

// ---------------------------------------------------------------------------
// Kernel C: split-fp16 mma.sync GEMM  g_x[M,128] = feat[M,512] @ W[512,128]
//   CTA: 128 rows x full N=128, K in 16 chunks of 32.
//   8 warps: warp (wm 0..3, wn 0..1) owns 32m x 64n -> 2 mfrag x 8 nfrag.
//   Per frag pair: 4 MMAs (hh, hl, lh, ll) into ONE f32 accumulator.
//   MMA issue is term-major / nf-minor so consecutive HMMAs hit different
//   accumulators (8 independent chains) while each accumulator still sees
//   the exact hh->hl->lh->ll order per k-step.
//   Smem rows padded to 36 halfs -> conflict-free frag LDS and STS.64.
// ---------------------------------------------------------------------------
#define PAD 36
#define NCH (IN_FEAT / 32)   // 16 chunks

__global__ void __launch_bounds__(256, 1) gemm_mma_kernel(const float* __restrict__ A) {
    __shared__ __half sAh[128 * PAD];
    __shared__ __half sAl[128 * PAD];
    __shared__ __half sBh[128 * PAD];
    __shared__ __half sBl[128 * PAD];

    const int tid  = threadIdx.x;
    const int lane = tid & 31;
    const int w    = tid >> 5;
    const int wm   = w & 3;            // m block (32 rows)
    const int wn   = w >> 2;           // n half (64 cols)
    const int g    = lane >> 2;        // 0..7
    const int t    = lane & 3;         // 0..3
    const int row0 = blockIdx.x * 128;

    // A loader: thread -> (row ar, 16-wide k half)
    const int ar = tid >> 1;
    const int ak = (tid & 1) * 16;
    const bool aok = (row0 + ar) < N_NODES;
    const float* Ap = A + (size_t)(row0 + ar) * IN_FEAT + ak;

    float4 aR[4];                       // 16 fp32 of A
    uint4  bhR[2], blR[2];              // 2x8 fp16 of Bh/Bl per thread

    auto prefetch = [&](int c) {
        #pragma unroll
        for (int j = 0; j < 4; j++)
            aR[j] = aok ? *reinterpret_cast<const float4*>(Ap + c * 32 + j * 4)
                        : make_float4(0.f, 0.f, 0.f, 0.f);
        #pragma unroll
        for (int j = 0; j < 2; j++) {
            const int u  = tid + 256 * j;         // 0..511 units of 8 halfs
            const int n  = u >> 2;
            const int kq = (u & 3) * 8;
            bhR[j] = *reinterpret_cast<const uint4*>(g_Bh + n * IN_FEAT + c * 32 + kq);
            blR[j] = *reinterpret_cast<const uint4*>(g_Bl + n * IN_FEAT + c * 32 + kq);
        }
    };

    float acc[2][8][4];
    #pragma unroll
    for (int mf = 0; mf < 2; mf++)
        #pragma unroll
        for (int nf = 0; nf < 8; nf++)
            #pragma unroll
            for (int i = 0; i < 4; i++) acc[mf][nf][i] = 0.0f;

    prefetch(0);

    for (int c = 0; c < NCH; c++) {
        // ---- store A (convert+split) and B into smem ----
        #pragma unroll
        for (int q = 0; q < 4; q++) {          // q: group of 4 floats
            __align__(8) __half hh[4], ll[4];
            const float* fp = reinterpret_cast<const float*>(&aR[q]);
            #pragma unroll
            for (int j = 0; j < 4; j++) split2(fp[j], hh[j], ll[j]);
            *reinterpret_cast<uint2*>(&sAh[ar * PAD + ak + q * 4]) = *reinterpret_cast<uint2*>(hh);
            *reinterpret_cast<uint2*>(&sAl[ar * PAD + ak + q * 4]) = *reinterpret_cast<uint2*>(ll);
        }
        #pragma unroll
        for (int j = 0; j < 2; j++) {
            const int u  = tid + 256 * j;
            const int n  = u >> 2;
            const int kq = (u & 3) * 8;
            const uint2* bh2 = reinterpret_cast<const uint2*>(&bhR[j]);
            const uint2* bl2 = reinterpret_cast<const uint2*>(&blR[j]);
            *reinterpret_cast<uint2*>(&sBh[n * PAD + kq])     = bh2[0];
            *reinterpret_cast<uint2*>(&sBh[n * PAD + kq + 4]) = bh2[1];
            *reinterpret_cast<uint2*>(&sBl[n * PAD + kq])     = bl2[0];
            *reinterpret_cast<uint2*>(&sBl[n * PAD + kq + 4]) = bl2[1];
        }
        __syncthreads();

        if (c + 1 < NCH) prefetch(c + 1);      // LDG overlaps compute

        // ---- compute: 2 k16 steps ----
        #pragma unroll
        for (int ks = 0; ks < 2; ks++) {
            const int ko = ks * 16;

            uint32_t bh[8][2], bl[8][2];
            #pragma unroll
            for (int nf = 0; nf < 8; nf++) {
                const int n = wn * 64 + nf * 8 + g;
                const __half* bp  = &sBh[n * PAD + ko + 2 * t];
                const __half* bp2 = &sBl[n * PAD + ko + 2 * t];
                bh[nf][0] = *reinterpret_cast<const uint32_t*>(bp);
                bh[nf][1] = *reinterpret_cast<const uint32_t*>(bp + 8);
                bl[nf][0] = *reinterpret_cast<const uint32_t*>(bp2);
                bl[nf][1] = *reinterpret_cast<const uint32_t*>(bp2 + 8);
            }

            #pragma unroll
            for (int mf = 0; mf < 2; mf++) {
                const int r = wm * 32 + mf * 16 + g;
                const __half* ap  = &sAh[r * PAD + ko + 2 * t];
                const __half* ap2 = &sAl[r * PAD + ko + 2 * t];
                uint32_t ah[4], al[4];
                ah[0] = *reinterpret_cast<const uint32_t*>(ap);
                ah[1] = *reinterpret_cast<const uint32_t*>(ap + 8 * PAD);
                ah[2] = *reinterpret_cast<const uint32_t*>(ap + 8);
                ah[3] = *reinterpret_cast<const uint32_t*>(ap + 8 * PAD + 8);
                al[0] = *reinterpret_cast<const uint32_t*>(ap2);
                al[1] = *reinterpret_cast<const uint32_t*>(ap2 + 8 * PAD);
                al[2] = *reinterpret_cast<const uint32_t*>(ap2 + 8);
                al[3] = *reinterpret_cast<const uint32_t*>(ap2 + 8 * PAD + 8);

                // term-major, nf-minor: consecutive MMAs target different
                // accumulators; per-accumulator order stays hh,hl,lh,ll.
                #pragma unroll
                for (int nf = 0; nf < 8; nf++) MMA16816(acc[mf][nf], ah, bh[nf]);
                #pragma unroll
                for (int nf = 0; nf < 8; nf++) MMA16816(acc[mf][nf], ah, bl[nf]);
                #pragma unroll
                for (int nf = 0; nf < 8; nf++) MMA16816(acc[mf][nf], al, bh[nf]);
                #pragma unroll
                for (int nf = 0; nf < 8; nf++) MMA16816(acc[mf][nf], al, bl[nf]);
            }
        }
        __syncthreads();
    }

    // ---- epilogue: acc -> g_x ----
    #pragma unroll
    for (int mf = 0; mf < 2; mf++) {
        const int r0 = row0 + wm * 32 + mf * 16 + g;
        #pragma unroll
        for (int nf = 0; nf < 8; nf++) {
            const int col = wn * 64 + nf * 8 + 2 * t;
            if (r0 < N_NODES) {
                float2 v = make_float2(acc[mf][nf][0], acc[mf][nf][1]);
                *reinterpret_cast<float2*>(g_x + (size_t)r0 * OUT_FEAT + col) = v;
            }
            if (r0 + 8 < N_NODES) {
                float2 v = make_float2(acc[mf][nf][2], acc[mf][nf][3]);
                *reinterpret_cast<float2*>(g_x + (size_t)(r0 + 8) * OUT_FEAT + col) = v;
            }
        }
    }
}

// ---------------------------------------------------------------------------
// Kernel D: SpMM + multispike. Warp per node, lane owns 4 cols, unroll 4.
// ---------------------------------------------------------------------------
__global__ void __launch_bounds__(256) spmm_kernel(const int*   __restrict__ cols,
                                                   const float* __restrict__ ew,
                                                   float*       __restrict__ out) {
    const int node = blockIdx.x * 8 + (threadIdx.x >> 5);
    if (node >= N_NODES) return;
    const int lane = threadIdx.x & 31;

    const int start = g_row_ptr[node];
    const int end   = g_row_ptr[node + 1];

    float4 acc = make_float4(0.f, 0.f, 0.f, 0.f);
    int e = start;
    for (; e + 4 <= end; e += 4) {
        const int   c0 = __ldg(cols + e),     c1 = __ldg(cols + e + 1);
        const int   c2 = __ldg(cols + e + 2), c3 = __ldg(cols + e + 3);
        const float w0 = __ldg(ew + e),       w1 = __ldg(ew + e + 1);
        const float w2 = __ldg(ew + e + 2),   w3 = __ldg(ew + e + 3);
        const float4 v0 = *reinterpret_cast<const float4*>(g_x + (size_t)c0 * OUT_FEAT + lane * 4);
        const float4 v1 = *reinterpret_cast<const float4*>(g_x + (size_t)c1 * OUT_FEAT + lane * 4);
        const float4 v2 = *reinterpret_cast<const float4*>(g_x + (size_t)c2 * OUT_FEAT + lane * 4);
        const float4 v3 = *reinterpret_cast<const float4*>(g_x + (size_t)c3 * OUT_FEAT + lane * 4);
        acc.x = fmaf(w0, v0.x, acc.x); acc.y = fmaf(w0, v0.y, acc.y);
        acc.z = fmaf(w0, v0.z, acc.z); acc.w = fmaf(w0, v0.w, acc.w);
        acc.x = fmaf(w1, v1.x, acc.x); acc.y = fmaf(w1, v1.y, acc.y);
        acc.z = fmaf(w1, v1.z, acc.z); acc.w = fmaf(w1, v1.w, acc.w);
        acc.x = fmaf(w2, v2.x, acc.x); acc.y = fmaf(w2, v2.y, acc.y);
        acc.z = fmaf(w2, v2.z, acc.z); acc.w = fmaf(w2, v2.w, acc.w);
        acc.x = fmaf(w3, v3.x, acc.x); acc.y = fmaf(w3, v3.y, acc.y);
        acc.z = fmaf(w3, v3.z, acc.z); acc.w = fmaf(w3, v3.w, acc.w);
    }
    for (; e < end; e++) {
        const int   c0 = __ldg(cols + e);
        const float w0 = __ldg(ew + e);
        const float4 v0 = *reinterpret_cast<const float4*>(g_x + (size_t)c0 * OUT_FEAT + lane * 4);
        acc.x = fmaf(w0, v0.x, acc.x); acc.y = fmaf(w0, v0.y, acc.y);
        acc.z = fmaf(w0, v0.z, acc.z); acc.w = fmaf(w0, v0.w, acc.w);
    }

    float4 o;
    o.x = floorf(fminf(fmaxf(4.f * acc.x, 0.f), 4.f) + 0.5f) * 0.25f;
    o.y = floorf(fminf(fmaxf(4.f * acc.y, 0.f), 4.f) + 0.5f) * 0.25f;
    o.z = floorf(fminf(fmaxf(4.f * acc.z, 0.f), 4.f) + 0.5f) * 0.25f;
    o.w = floorf(fminf(fmaxf(4.f * acc.w, 0.f), 4.f) + 0.5f) * 0.25f;
    *reinterpret_cast<float4*>(out + (size_t)node * OUT_FEAT + lane * 4) = o;
}

// ---------------------------------------------------------------------------
extern "C" void kernel_launch(void* const* d_in, const int* in_sizes, int n_in,
                              void* d_out, int out_size) {
    const float* feat   = (const float*)d_in[0];
    const float* weight = (const float*)d_in[1];
    const int*   rows   = (const int*)  d_in[2];
    const int*   cols   = (const int*)  d_in[3];
    const float* ew     = (const float*)d_in[4];
    float*       out    = (float*)d_out;

    bsplit_kernel<<<(IN_FEAT * OUT_FEAT + 255) / 256, 256>>>(weight);
    build_rowptr_kernel<<<(N_EDGES + 255) / 256, 256>>>(rows);
    gemm_mma_kernel<<<(N_NODES + 127) / 128, 256>>>(feat);
    spmm_kernel<<<(N_NODES + 7) / 8, 256>>>(cols, ew, out);
}

// round 15
// speedup vs baseline: 2.6101x; 1.0098x over previous
#include <cuda_runtime.h>
#include <cuda_fp16.h>
#include <cstdint>

#define N_NODES 50000
#define IN_FEAT 512
#define OUT_FEAT 128
#define N_EDGES 800000

// ---------------------------------------------------------------------------
// Scratch (allocations forbidden -> device globals)
// ---------------------------------------------------------------------------
__device__ float  g_x[(size_t)N_NODES * OUT_FEAT];     // GEMM result (25.6 MB)
__device__ int    g_row_ptr[N_NODES + 1];
__device__ __half g_Bh[OUT_FEAT * IN_FEAT];            // W^T hi  [128 n][512 k]
__device__ __half g_Bl[OUT_FEAT * IN_FEAT];            // W^T lo  (unscaled residual)

// ---------------------------------------------------------------------------
// fp16 2-way split: a = h + l + r,  |r| <~ 2^-22 |a|
// ---------------------------------------------------------------------------
__device__ __forceinline__ void split2(float a, __half& h, __half& l) {
    h = __float2half_rn(a);
    l = __float2half_rn(a - __half2float(h));
}

// mma.sync m16n8k16 f16 -> f32 (plain sm_80+ ISA; assembles at sm_103)
#define MMA16816(c, a, b)                                                     \
    asm volatile(                                                             \
        "mma.sync.aligned.m16n8k16.row.col.f32.f16.f16.f32 "                  \
        "{%0,%1,%2,%3}, {%4,%5,%6,%7}, {%8,%9}, {%0,%1,%2,%3};"               \
        : "+f"((c)[0]), "+f"((c)[1]), "+f"((c)[2]), "+f"((c)[3])              \
        : "r"((a)[0]), "r"((a)[1]), "r"((a)[2]), "r"((a)[3]),                 \
          "r"((b)[0]), "r"((b)[1]))

// ---------------------------------------------------------------------------
// Kernel A: split W (fp32 [512,128]) into transposed fp16 hi/lo [128][512]
// ---------------------------------------------------------------------------
__global__ void __launch_bounds__(256) bsplit_kernel(const float* __restrict__ W) {
    const int idx = blockIdx.x * 256 + threadIdx.x;
    if (idx >= IN_FEAT * OUT_FEAT) return;
    const int k = idx >> 7;
    const int n = idx & 127;
    __half h, l;
    split2(W[idx], h, l);
    const int o = n * IN_FEAT + k;
    g_Bh[o] = h;
    g_Bl[o] = l;
}

// ---------------------------------------------------------------------------
// Kernel B: row_ptr from sorted rows
// ---------------------------------------------------------------------------
__global__ void __launch_bounds__(256) build_rowptr_kernel(const int* __restrict__ rows) {
    const int e = blockIdx.x * 256 + threadIdx.x;
    if (e >= N_EDGES) return;
    const int r    = rows[e];
    const int prev = (e == 0) ? -1 : rows[e - 1];
    for (int i = prev + 1; i <= r; i++) g_row_ptr[i] = e;
    if (e == N_EDGES - 1)
        for (int i = r + 1; i <= N_NODES; i++) g_row_ptr[i] = N_EDGES;
}

// ---------------------------------------------------------------------------
// Kernel C: split-fp16 mma.sync GEMM  g_x[M,128] = feat[M,512] @ W[512,128]
//   CTA: BM=64 rows x full N=128, K in 16 chunks of 32. 256 thr, 2 CTAs/SM.
//   8 warps: (wm 0..1, wn 0..3) -> warp owns 32m x 32n = 2 mfrag x 4 nfrag.
//   Per frag pair: 4 MMAs (hh, hl, lh, ll) into ONE f32 accumulator;
//   term-major / nf-minor issue; per-accumulator order identical to R14.
//   Smem rows padded to 36 halfs -> conflict-free frag LDS and STS.64.
// ---------------------------------------------------------------------------
#define PAD 36
#define NCH (IN_FEAT / 32)   // 16 chunks
#define BM 64

__global__ void __launch_bounds__(256, 2) gemm_mma_kernel(const float* __restrict__ A) {
    __shared__ __half sAh[BM * PAD];
    __shared__ __half sAl[BM * PAD];
    __shared__ __half sBh[128 * PAD];
    __shared__ __half sBl[128 * PAD];

    const int tid  = threadIdx.x;
    const int lane = tid & 31;
    const int w    = tid >> 5;
    const int wm   = w & 1;            // m block (32 rows)
    const int wn   = w >> 1;           // n block (32 cols)
    const int g    = lane >> 2;        // 0..7
    const int t    = lane & 3;         // 0..3
    const int row0 = blockIdx.x * BM;

    // A loader: thread -> (row ar, 8-wide k slice)
    const int ar = tid >> 2;               // 0..63
    const int ak = (tid & 3) * 8;          // 0,8,16,24
    const bool aok = (row0 + ar) < N_NODES;
    const float* Ap = A + (size_t)(row0 + ar) * IN_FEAT + ak;

    float4 aR[2];                       // 8 fp32 of A
    uint4  bhR[2], blR[2];              // 2x8 fp16 of Bh/Bl per thread

    auto prefetch = [&](int c) {
        #pragma unroll
        for (int j = 0; j < 2; j++)
            aR[j] = aok ? *reinterpret_cast<const float4*>(Ap + c * 32 + j * 4)
                        : make_float4(0.f, 0.f, 0.f, 0.f);
        #pragma unroll
        for (int j = 0; j < 2; j++) {
            const int u  = tid + 256 * j;         // 0..511 units of 8 halfs
            const int n  = u >> 2;
            const int kq = (u & 3) * 8;
            bhR[j] = *reinterpret_cast<const uint4*>(g_Bh + n * IN_FEAT + c * 32 + kq);
            blR[j] = *reinterpret_cast<const uint4*>(g_Bl + n * IN_FEAT + c * 32 + kq);
        }
    };

    float acc[2][4][4];
    #pragma unroll
    for (int mf = 0; mf < 2; mf++)
        #pragma unroll
        for (int nf = 0; nf < 4; nf++)
            #pragma unroll
            for (int i = 0; i < 4; i++) acc[mf][nf][i] = 0.0f;

    prefetch(0);

    for (int c = 0; c < NCH; c++) {
        // ---- store A (convert+split) and B into smem ----
        #pragma unroll
        for (int q = 0; q < 2; q++) {          // q: group of 4 floats
            __align__(8) __half hh[4], ll[4];
            const float* fp = reinterpret_cast<const float*>(&aR[q]);
            #pragma unroll
            for (int j = 0; j < 4; j++) split2(fp[j], hh[j], ll[j]);
            *reinterpret_cast<uint2*>(&sAh[ar * PAD + ak + q * 4]) = *reinterpret_cast<uint2*>(hh);
            *reinterpret_cast<uint2*>(&sAl[ar * PAD + ak + q * 4]) = *reinterpret_cast<uint2*>(ll);
        }
        #pragma unroll
        for (int j = 0; j < 2; j++) {
            const int u  = tid + 256 * j;
            const int n  = u >> 2;
            const int kq = (u & 3) * 8;
            const uint2* bh2 = reinterpret_cast<const uint2*>(&bhR[j]);
            const uint2* bl2 = reinterpret_cast<const uint2*>(&blR[j]);
            *reinterpret_cast<uint2*>(&sBh[n * PAD + kq])     = bh2[0];
            *reinterpret_cast<uint2*>(&sBh[n * PAD + kq + 4]) = bh2[1];
            *reinterpret_cast<uint2*>(&sBl[n * PAD + kq])     = bl2[0];
            *reinterpret_cast<uint2*>(&sBl[n * PAD + kq + 4]) = bl2[1];
        }
        __syncthreads();

        if (c + 1 < NCH) prefetch(c + 1);      // LDG overlaps compute

        // ---- compute: 2 k16 steps ----
        #pragma unroll
        for (int ks = 0; ks < 2; ks++) {
            const int ko = ks * 16;

            uint32_t bh[4][2], bl[4][2];
            #pragma unroll
            for (int nf = 0; nf < 4; nf++) {
                const int n = wn * 32 + nf * 8 + g;
                const __half* bp  = &sBh[n * PAD + ko + 2 * t];
                const __half* bp2 = &sBl[n * PAD + ko + 2 * t];
                bh[nf][0] = *reinterpret_cast<const uint32_t*>(bp);
                bh[nf][1] = *reinterpret_cast<const uint32_t*>(bp + 8);
                bl[nf][0] = *reinterpret_cast<const uint32_t*>(bp2);
                bl[nf][1] = *reinterpret_cast<const uint32_t*>(bp2 + 8);
            }

            #pragma unroll
            for (int mf = 0; mf < 2; mf++) {
                const int r = wm * 32 + mf * 16 + g;
                const __half* ap  = &sAh[r * PAD + ko + 2 * t];
                const __half* ap2 = &sAl[r * PAD + ko + 2 * t];
                uint32_t ah[4], al[4];
                ah[0] = *reinterpret_cast<const uint32_t*>(ap);
                ah[1] = *reinterpret_cast<const uint32_t*>(ap + 8 * PAD);
                ah[2] = *reinterpret_cast<const uint32_t*>(ap + 8);
                ah[3] = *reinterpret_cast<const uint32_t*>(ap + 8 * PAD + 8);
                al[0] = *reinterpret_cast<const uint32_t*>(ap2);
                al[1] = *reinterpret_cast<const uint32_t*>(ap2 + 8 * PAD);
                al[2] = *reinterpret_cast<const uint32_t*>(ap2 + 8);
                al[3] = *reinterpret_cast<const uint32_t*>(ap2 + 8 * PAD + 8);

                // term-major, nf-minor: consecutive MMAs target different
                // accumulators; per-accumulator order stays hh,hl,lh,ll.
                #pragma unroll
                for (int nf = 0; nf < 4; nf++) MMA16816(acc[mf][nf], ah, bh[nf]);
                #pragma unroll
                for (int nf = 0; nf < 4; nf++) MMA16816(acc[mf][nf], ah, bl[nf]);
                #pragma unroll
                for (int nf = 0; nf < 4; nf++) MMA16816(acc[mf][nf], al, bh[nf]);
                #pragma unroll
                for (int nf = 0; nf < 4; nf++) MMA16816(acc[mf][nf], al, bl[nf]);
            }
        }
        __syncthreads();
    }

    // ---- epilogue: acc -> g_x ----
    #pragma unroll
    for (int mf = 0; mf < 2; mf++) {
        const int r0 = row0 + wm * 32 + mf * 16 + g;
        #pragma unroll
        for (int nf = 0; nf < 4; nf++) {
            const int col = wn * 32 + nf * 8 + 2 * t;
            if (r0 < N_NODES) {
                float2 v = make_float2(acc[mf][nf][0], acc[mf][nf][1]);
                *reinterpret_cast<float2*>(g_x + (size_t)r0 * OUT_FEAT + col) = v;
            }
            if (r0 + 8 < N_NODES) {
                float2 v = make_float2(acc[mf][nf][2], acc[mf][nf][3]);
                *reinterpret_cast<float2*>(g_x + (size_t)(r0 + 8) * OUT_FEAT + col) = v;
            }
        }
    }
}

// ---------------------------------------------------------------------------
// Kernel D: SpMM + multispike. Warp per node, lane owns 4 cols, unroll 4.
// ---------------------------------------------------------------------------
__global__ void __launch_bounds__(256) spmm_kernel(const int*   __restrict__ cols,
                                                   const float* __restrict__ ew,
                                                   float*       __restrict__ out) {
    const int node = blockIdx.x * 8 + (threadIdx.x >> 5);
    if (node >= N_NODES) return;
    const int lane = threadIdx.x & 31;

    const int start = g_row_ptr[node];
    const int end   = g_row_ptr[node + 1];

    float4 acc = make_float4(0.f, 0.f, 0.f, 0.f);
    int e = start;
    for (; e + 4 <= end; e += 4) {
        const int   c0 = __ldg(cols + e),     c1 = __ldg(cols + e + 1);
        const int   c2 = __ldg(cols + e + 2), c3 = __ldg(cols + e + 3);
        const float w0 = __ldg(ew + e),       w1 = __ldg(ew + e + 1);
        const float w2 = __ldg(ew + e + 2),   w3 = __ldg(ew + e + 3);
        const float4 v0 = *reinterpret_cast<const float4*>(g_x + (size_t)c0 * OUT_FEAT + lane * 4);
        const float4 v1 = *reinterpret_cast<const float4*>(g_x + (size_t)c1 * OUT_FEAT + lane * 4);
        const float4 v2 = *reinterpret_cast<const float4*>(g_x + (size_t)c2 * OUT_FEAT + lane * 4);
        const float4 v3 = *reinterpret_cast<const float4*>(g_x + (size_t)c3 * OUT_FEAT + lane * 4);
        acc.x = fmaf(w0, v0.x, acc.x); acc.y = fmaf(w0, v0.y, acc.y);
        acc.z = fmaf(w0, v0.z, acc.z); acc.w = fmaf(w0, v0.w, acc.w);
        acc.x = fmaf(w1, v1.x, acc.x); acc.y = fmaf(w1, v1.y, acc.y);
        acc.z = fmaf(w1, v1.z, acc.z); acc.w = fmaf(w1, v1.w, acc.w);
        acc.x = fmaf(w2, v2.x, acc.x); acc.y = fmaf(w2, v2.y, acc.y);
        acc.z = fmaf(w2, v2.z, acc.z); acc.w = fmaf(w2, v2.w, acc.w);
        acc.x = fmaf(w3, v3.x, acc.x); acc.y = fmaf(w3, v3.y, acc.y);
        acc.z = fmaf(w3, v3.z, acc.z); acc.w = fmaf(w3, v3.w, acc.w);
    }
    for (; e < end; e++) {
        const int   c0 = __ldg(cols + e);
        const float w0 = __ldg(ew + e);
        const float4 v0 = *reinterpret_cast<const float4*>(g_x + (size_t)c0 * OUT_FEAT + lane * 4);
        acc.x = fmaf(w0, v0.x, acc.x); acc.y = fmaf(w0, v0.y, acc.y);
        acc.z = fmaf(w0, v0.z, acc.z); acc.w = fmaf(w0, v0.w, acc.w);
    }

    float4 o;
    o.x = floorf(fminf(fmaxf(4.f * acc.x, 0.f), 4.f) + 0.5f) * 0.25f;
    o.y = floorf(fminf(fmaxf(4.f * acc.y, 0.f), 4.f) + 0.5f) * 0.25f;
    o.z = floorf(fminf(fmaxf(4.f * acc.z, 0.f), 4.f) + 0.5f) * 0.25f;
    o.w = floorf(fminf(fmaxf(4.f * acc.w, 0.f), 4.f) + 0.5f) * 0.25f;
    *reinterpret_cast<float4*>(out + (size_t)node * OUT_FEAT + lane * 4) = o;
}

// ---------------------------------------------------------------------------
extern "C" void kernel_launch(void* const* d_in, const int* in_sizes, int n_in,
                              void* d_out, int out_size) {
    const float* feat   = (const float*)d_in[0];
    const float* weight = (const float*)d_in[1];
    const int*   rows   = (const int*)  d_in[2];
    const int*   cols   = (const int*)  d_in[3];
    const float* ew     = (const float*)d_in[4];
    float*       out    = (float*)d_out;

    bsplit_kernel<<<(IN_FEAT * OUT_FEAT + 255) / 256, 256>>>(weight);
    build_rowptr_kernel<<<(N_EDGES + 255) / 256, 256>>>(rows);
    gemm_mma_kernel<<<(N_NODES + BM - 1) / BM, 256>>>(feat);
    spmm_kernel<<<(N_NODES + 7) / 8, 256>>>(cols, ew, out);
}